// round 6
// baseline (speedup 1.0000x reference)
#include <cuda_runtime.h>
#include <cuda_fp16.h>
#include <cstdint>
#include <math.h>

#define T 2048        // B*S tokens
#define D 1024
#define Hh 2048
#define E 8
#define TWOH 4096
#define NSLOT (T * 2)

// ---- scratch ----
__device__ int    g_cnt[E];
__device__ int    g_list[E][T];
__device__ float  g_wt[NSLOT];
__device__ __half g_xh[(size_t)T * D];            // fp16 x (4 MB)
__device__ __half g_hiddenh[(size_t)NSLOT * Hh];  // fp16 hidden (16 MB)
__device__ float  g_yslot[(size_t)NSLOT * D];     // 16 MB
__device__ float  g_aux;

// ======================= helpers =======================
__device__ __forceinline__ uint32_t smem_u32(const void* p) {
    uint32_t a;
    asm("{ .reg .u64 t; cvta.to.shared.u64 t, %1; cvt.u32.u64 %0, t; }" : "=r"(a) : "l"(p));
    return a;
}
__device__ __forceinline__ uint32_t h2u(__half2 h) { return *(uint32_t*)&h; }

#define CP_ASYNC16(dst, src) \
    asm volatile("cp.async.cg.shared.global [%0], [%1], 16;" :: "r"(dst), "l"(src))
#define CP_COMMIT() asm volatile("cp.async.commit_group;")
#define CP_WAIT0()  asm volatile("cp.async.wait_group 0;" ::: "memory")

__device__ __forceinline__ void ldsm4(uint32_t* r, uint32_t addr) {
    asm volatile("ldmatrix.sync.aligned.m8n8.x4.shared.b16 {%0,%1,%2,%3},[%4];"
        : "=r"(r[0]), "=r"(r[1]), "=r"(r[2]), "=r"(r[3]) : "r"(addr));
}
__device__ __forceinline__ void ldsm4t(uint32_t* r, uint32_t addr) {
    asm volatile("ldmatrix.sync.aligned.m8n8.x4.trans.shared.b16 {%0,%1,%2,%3},[%4];"
        : "=r"(r[0]), "=r"(r[1]), "=r"(r[2]), "=r"(r[3]) : "r"(addr));
}
__device__ __forceinline__ void mma16(float* c, const uint32_t* a, uint32_t b0, uint32_t b1) {
    asm volatile(
        "mma.sync.aligned.m16n8k16.row.col.f32.f16.f16.f32 "
        "{%0,%1,%2,%3},{%4,%5,%6,%7},{%8,%9},{%0,%1,%2,%3};"
        : "+f"(c[0]), "+f"(c[1]), "+f"(c[2]), "+f"(c[3])
        : "r"(a[0]), "r"(a[1]), "r"(a[2]), "r"(a[3]), "r"(b0), "r"(b1));
}

// ======================= small kernels =======================
__global__ void zero_kernel() {
    int i = threadIdx.x;
    if (i < E) g_cnt[i] = 0;
    if (i == 0) g_aux = 0.0f;
}

__global__ void prep_x(const float* __restrict__ x) {
    int i = blockIdx.x * blockDim.x + threadIdx.x;
    if (i < T * D / 4) {
        float4 v = ((const float4*)x)[i];
        uint2 u;
        u.x = h2u(__floats2half2_rn(v.x, v.y));
        u.y = h2u(__floats2half2_rn(v.z, v.w));
        ((uint2*)g_xh)[i] = u;
    }
}

__global__ void router_kernel(const float* __restrict__ x,
                              const float* __restrict__ rw,
                              const float* __restrict__ rb) {
    int warp = threadIdx.x >> 5;
    int lane = threadIdx.x & 31;
    int t = blockIdx.x * (blockDim.x >> 5) + warp;
    if (t >= T) return;

    const float* xr = x + (size_t)t * D;
    float acc[E];
#pragma unroll
    for (int e = 0; e < E; e++) acc[e] = 0.0f;
    for (int d = lane; d < D; d += 32) {
        float xv = xr[d];
#pragma unroll
        for (int e = 0; e < E; e++) acc[e] += xv * rw[e * D + d];
    }
#pragma unroll
    for (int e = 0; e < E; e++) {
#pragma unroll
        for (int off = 16; off; off >>= 1)
            acc[e] += __shfl_xor_sync(0xffffffffu, acc[e], off);
    }
    if (lane == 0) {
        float score[E];
        float auxl = 0.0f;
#pragma unroll
        for (int e = 0; e < E; e++) {
            float lg = acc[e] + rb[e];
            auxl += lg * lg;
            score[e] = 1.0f / (1.0f + expf(-lg));
        }
        int e0 = 0;
#pragma unroll
        for (int e = 1; e < E; e++) if (score[e] > score[e0]) e0 = e;
        int e1 = -1;
#pragma unroll
        for (int e = 0; e < E; e++) {
            if (e == e0) continue;
            if (e1 < 0 || score[e] > score[e1]) e1 = e;
        }
        float s0 = score[e0], s1 = score[e1];
        float inv = 1.0f / (s0 + s1 + 1e-6f);
        g_wt[2 * t]     = s0 * inv;
        g_wt[2 * t + 1] = s1 * inv;
        int p0 = atomicAdd(&g_cnt[e0], 1); g_list[e0][p0] = 2 * t;
        int p1 = atomicAdd(&g_cnt[e1], 1); g_list[e1][p1] = 2 * t + 1;
        atomicAdd(&g_aux, auxl);
    }
}

// combine + aux fused
__global__ void combine_kernel(float* __restrict__ out, int out_size) {
    int i = blockIdx.x * blockDim.x + threadIdx.x;
    if (i == 0 && out_size > T * D)
        out[T * D] = 0.01f * g_aux / (float)(T * E);
    const int total = T * D / 4;
    if (i >= total) return;
    int t = i / (D / 4);
    int j = i % (D / 4);
    float4 a = ((const float4*)(g_yslot + (size_t)(2 * t) * D))[j];
    float4 b = ((const float4*)(g_yslot + (size_t)(2 * t + 1) * D))[j];
    float4 o = {a.x + b.x, a.y + b.y, a.z + b.z, a.w + b.w};
    ((float4*)out)[i] = o;
}

// ======================= GEMM common layout =======================
// slot[256]@0, tok/src[256]@1024
// A: [m:256][k:64] fp16, row stride 144B. stage = 36864B
// B: [k:64][n:64+8pad] fp16, row stride 144B. stage = 9216B
#define A_OFF 2048
#define A_STG 36864
#define B_OFF (2048 + 2 * 36864)
#define B_STG 9216
#define G_SMEM (B_OFF + 2 * 9216)

// ======================= GEMM1 =======================
// 256m x 32n dual (W1 cols n0..n0+31 in B[:,0:32), W2 in B[:,32:64)).
// 8 warps, warp w owns rows [32w, 32w+32). KC=64, 16 chunks.
__global__ void __launch_bounds__(256, 2) gemm1_kernel(const float* __restrict__ w12) {
    int e = blockIdx.z;
    int cnt = g_cnt[e];
    int m0 = blockIdx.x * 256;
    if (m0 >= cnt) return;
    int n0 = blockIdx.y * 32;

    extern __shared__ char smem[];
    uint32_t sb = smem_u32(smem);
    int* slot = (int*)smem;
    int* tok  = (int*)(smem + 1024);
    int tid = threadIdx.x, wid = tid >> 5, lane = tid & 31;
    int g = lane >> 2, tg = lane & 3;
    int wm = wid * 32;
    int q = lane >> 3, r = lane & 7;

#pragma unroll
    for (int j = 0; j < 1; j++) {
        int m = m0 + tid;
        int s = g_list[e][(m < cnt) ? m : 0];
        slot[tid] = (m < cnt) ? s : -1;
        tok[tid]  = s >> 1;
    }
    __syncthreads();

    const float* wb0 = w12 + (size_t)e * D * TWOH;
    uint32_t aBase = sb + A_OFF + (uint32_t)((wm + (q & 1) * 8 + r) * 144 + (q >> 1) * 16);
    uint32_t bBase = sb + B_OFF + (uint32_t)(((q & 1) * 8 + r) * 144 + (q >> 1) * 16);

    float4 rbv[4];

    // ---- prologue ----
#pragma unroll
    for (int j = 0; j < 8; j++) {
        int c = tid + j * 256;
        int m = c >> 3, kq = c & 7;
        const __half* src = g_xh + (size_t)tok[m] * D + kq * 8;
        CP_ASYNC16(sb + A_OFF + m * 144 + kq * 16, src);
    }
    CP_COMMIT();
#pragma unroll
    for (int j = 0; j < 4; j++) {
        int c = tid + j * 256;
        int k = c >> 4, f4 = c & 15;
        int col = (f4 < 8) ? (n0 + f4 * 4) : (Hh + n0 + (f4 - 8) * 4);
        rbv[j] = *(const float4*)(wb0 + (size_t)k * TWOH + col);
    }
#pragma unroll
    for (int j = 0; j < 4; j++) {
        int c = tid + j * 256;
        int k = c >> 4, f4 = c & 15;
        int dcol = (f4 < 8) ? (f4 * 4) : (32 + (f4 - 8) * 4);
        uint2 u;
        u.x = h2u(__floats2half2_rn(rbv[j].x, rbv[j].y));
        u.y = h2u(__floats2half2_rn(rbv[j].z, rbv[j].w));
        *(uint2*)(smem + B_OFF + k * 144 + dcol * 2) = u;
    }
    CP_WAIT0();
    __syncthreads();

    float acc1[2][4][4] = {}, acc2[2][4][4] = {};

    for (int i = 0; i < 16; i++) {
        int cur = i & 1, nxt = cur ^ 1;
        if (i + 1 < 16) {
            int k0 = (i + 1) * 64;
#pragma unroll
            for (int j = 0; j < 8; j++) {
                int c = tid + j * 256;
                int m = c >> 3, kq = c & 7;
                const __half* src = g_xh + (size_t)tok[m] * D + k0 + kq * 8;
                CP_ASYNC16(sb + A_OFF + nxt * A_STG + m * 144 + kq * 16, src);
            }
            CP_COMMIT();
#pragma unroll
            for (int j = 0; j < 4; j++) {
                int c = tid + j * 256;
                int k = c >> 4, f4 = c & 15;
                int col = (f4 < 8) ? (n0 + f4 * 4) : (Hh + n0 + (f4 - 8) * 4);
                rbv[j] = *(const float4*)(wb0 + (size_t)(k0 + k) * TWOH + col);
            }
        }
        // compute on cur
        {
            uint32_t aA = aBase + cur * A_STG;
            uint32_t bA = bBase + cur * B_STG;
#pragma unroll
            for (int kt = 0; kt < 4; kt++) {
                uint32_t a[2][4];
                ldsm4(a[0], aA + kt * 32);
                ldsm4(a[1], aA + kt * 32 + 16 * 144);
                uint32_t b1[8], b2[8];
                uint32_t bk = bA + kt * (16 * 144);
                ldsm4t(b1 + 0, bk + 0);
                ldsm4t(b1 + 4, bk + 16 * 2);
                ldsm4t(b2 + 0, bk + 32 * 2);
                ldsm4t(b2 + 4, bk + 48 * 2);
#pragma unroll
                for (int nt = 0; nt < 4; nt++) {
#pragma unroll
                    for (int mt = 0; mt < 2; mt++) {
                        mma16(acc1[mt][nt], a[mt], b1[2 * nt], b1[2 * nt + 1]);
                        mma16(acc2[mt][nt], a[mt], b2[2 * nt], b2[2 * nt + 1]);
                    }
                }
            }
        }
        if (i + 1 < 16) {
#pragma unroll
            for (int j = 0; j < 4; j++) {
                int c = tid + j * 256;
                int k = c >> 4, f4 = c & 15;
                int dcol = (f4 < 8) ? (f4 * 4) : (32 + (f4 - 8) * 4);
                uint2 u;
                u.x = h2u(__floats2half2_rn(rbv[j].x, rbv[j].y));
                u.y = h2u(__floats2half2_rn(rbv[j].z, rbv[j].w));
                *(uint2*)(smem + B_OFF + nxt * B_STG + k * 144 + dcol * 2) = u;
            }
        }
        CP_WAIT0();
        __syncthreads();
    }

    // epilogue: swiglu fuse, store fp16 hidden
#pragma unroll
    for (int mt = 0; mt < 2; mt++) {
        int r0 = wm + mt * 16 + g;
        int s0 = slot[r0], s1 = slot[r0 + 8];
#pragma unroll
        for (int nt = 0; nt < 4; nt++) {
            int col = n0 + nt * 8 + tg * 2;
            if (s0 >= 0) {
                float h1a = acc1[mt][nt][0], h2a = acc2[mt][nt][0];
                float h1b = acc1[mt][nt][1], h2b = acc2[mt][nt][1];
                float oa = h2a * h1a / (1.0f + expf(-h1a));
                float ob = h2b * h1b / (1.0f + expf(-h1b));
                *(uint32_t*)(g_hiddenh + (size_t)s0 * Hh + col) = h2u(__floats2half2_rn(oa, ob));
            }
            if (s1 >= 0) {
                float h1a = acc1[mt][nt][2], h2a = acc2[mt][nt][2];
                float h1b = acc1[mt][nt][3], h2b = acc2[mt][nt][3];
                float oa = h2a * h1a / (1.0f + expf(-h1a));
                float ob = h2b * h1b / (1.0f + expf(-h1b));
                *(uint32_t*)(g_hiddenh + (size_t)s1 * Hh + col) = h2u(__floats2half2_rn(oa, ob));
            }
        }
    }
}

// ======================= GEMM2 =======================
// 256m x 64n. 8 warps, warp w owns rows [32w, 32w+32). KC=64, 32 chunks.
__global__ void __launch_bounds__(256, 2) gemm2_kernel(const float* __restrict__ w3) {
    int e = blockIdx.z;
    int cnt = g_cnt[e];
    int m0 = blockIdx.x * 256;
    if (m0 >= cnt) return;
    int n0 = blockIdx.y * 64;

    extern __shared__ char smem[];
    uint32_t sb = smem_u32(smem);
    int* slot = (int*)smem;
    int* srcs = (int*)(smem + 1024);
    int tid = threadIdx.x, wid = tid >> 5, lane = tid & 31;
    int g = lane >> 2, tg = lane & 3;
    int wm = wid * 32;
    int q = lane >> 3, r = lane & 7;

    {
        int m = m0 + tid;
        int s = g_list[e][(m < cnt) ? m : 0];
        slot[tid] = (m < cnt) ? s : -1;
        srcs[tid] = s;
    }
    __syncthreads();

    const float* wb0 = w3 + (size_t)e * Hh * D + n0;
    uint32_t aBase = sb + A_OFF + (uint32_t)((wm + (q & 1) * 8 + r) * 144 + (q >> 1) * 16);
    uint32_t bBase = sb + B_OFF + (uint32_t)(((q & 1) * 8 + r) * 144 + (q >> 1) * 16);

    float4 rbv[4];

#pragma unroll
    for (int j = 0; j < 8; j++) {
        int c = tid + j * 256;
        int m = c >> 3, kq = c & 7;
        const __half* src = g_hiddenh + (size_t)srcs[m] * Hh + kq * 8;
        CP_ASYNC16(sb + A_OFF + m * 144 + kq * 16, src);
    }
    CP_COMMIT();
#pragma unroll
    for (int j = 0; j < 4; j++) {
        int c = tid + j * 256;
        int k = c >> 4, f4 = c & 15;
        rbv[j] = *(const float4*)(wb0 + (size_t)k * D + f4 * 4);
    }
#pragma unroll
    for (int j = 0; j < 4; j++) {
        int c = tid + j * 256;
        int k = c >> 4, f4 = c & 15;
        uint2 u;
        u.x = h2u(__floats2half2_rn(rbv[j].x, rbv[j].y));
        u.y = h2u(__floats2half2_rn(rbv[j].z, rbv[j].w));
        *(uint2*)(smem + B_OFF + k * 144 + f4 * 8) = u;
    }
    CP_WAIT0();
    __syncthreads();

    float acc[2][8][4] = {};

    for (int i = 0; i < 32; i++) {
        int cur = i & 1, nxt = cur ^ 1;
        if (i + 1 < 32) {
            int k0 = (i + 1) * 64;
#pragma unroll
            for (int j = 0; j < 8; j++) {
                int c = tid + j * 256;
                int m = c >> 3, kq = c & 7;
                const __half* src = g_hiddenh + (size_t)srcs[m] * Hh + k0 + kq * 8;
                CP_ASYNC16(sb + A_OFF + nxt * A_STG + m * 144 + kq * 16, src);
            }
            CP_COMMIT();
#pragma unroll
            for (int j = 0; j < 4; j++) {
                int c = tid + j * 256;
                int k = c >> 4, f4 = c & 15;
                rbv[j] = *(const float4*)(wb0 + (size_t)(k0 + k) * D + f4 * 4);
            }
        }
        {
            uint32_t aA = aBase + cur * A_STG;
            uint32_t bA = bBase + cur * B_STG;
#pragma unroll
            for (int kt = 0; kt < 4; kt++) {
                uint32_t a[2][4];
                ldsm4(a[0], aA + kt * 32);
                ldsm4(a[1], aA + kt * 32 + 16 * 144);
                uint32_t b[16];
                uint32_t bk = bA + kt * (16 * 144);
                ldsm4t(b + 0,  bk + 0);
                ldsm4t(b + 4,  bk + 16 * 2);
                ldsm4t(b + 8,  bk + 32 * 2);
                ldsm4t(b + 12, bk + 48 * 2);
#pragma unroll
                for (int nt = 0; nt < 8; nt++) {
#pragma unroll
                    for (int mt = 0; mt < 2; mt++)
                        mma16(acc[mt][nt], a[mt], b[2 * nt], b[2 * nt + 1]);
                }
            }
        }
        if (i + 1 < 32) {
#pragma unroll
            for (int j = 0; j < 4; j++) {
                int c = tid + j * 256;
                int k = c >> 4, f4 = c & 15;
                uint2 u;
                u.x = h2u(__floats2half2_rn(rbv[j].x, rbv[j].y));
                u.y = h2u(__floats2half2_rn(rbv[j].z, rbv[j].w));
                *(uint2*)(smem + B_OFF + nxt * B_STG + k * 144 + f4 * 8) = u;
            }
        }
        CP_WAIT0();
        __syncthreads();
    }

#pragma unroll
    for (int mt = 0; mt < 2; mt++) {
        int r0 = wm + mt * 16 + g;
        int s0 = slot[r0], s1 = slot[r0 + 8];
        float w0 = (s0 >= 0) ? g_wt[s0] : 0.0f;
        float w1 = (s1 >= 0) ? g_wt[s1] : 0.0f;
#pragma unroll
        for (int nt = 0; nt < 8; nt++) {
            int col = n0 + nt * 8 + tg * 2;
            if (s0 >= 0) {
                float2 v = {w0 * acc[mt][nt][0], w0 * acc[mt][nt][1]};
                *(float2*)(g_yslot + (size_t)s0 * D + col) = v;
            }
            if (s1 >= 0) {
                float2 v = {w1 * acc[mt][nt][2], w1 * acc[mt][nt][3]};
                *(float2*)(g_yslot + (size_t)s1 * D + col) = v;
            }
        }
    }
}

// ======================= launch =======================
extern "C" void kernel_launch(void* const* d_in, const int* in_sizes, int n_in,
                              void* d_out, int out_size) {
    const float* x   = (const float*)d_in[0];
    const float* rw  = (const float*)d_in[1];
    const float* rb  = (const float*)d_in[2];
    const float* w12 = (const float*)d_in[3];
    const float* w3  = (const float*)d_in[4];
    float* out = (float*)d_out;

    cudaFuncSetAttribute(gemm1_kernel, cudaFuncAttributeMaxDynamicSharedMemorySize, G_SMEM);
    cudaFuncSetAttribute(gemm2_kernel, cudaFuncAttributeMaxDynamicSharedMemorySize, G_SMEM);

    zero_kernel<<<1, 32>>>();                                   // 0
    prep_x<<<(T * D / 4 + 255) / 256, 256>>>(x);                // 1
    router_kernel<<<T / 8, 256>>>(x, rw, rb);                   // 2
    gemm1_kernel<<<dim3(8, 64, E), 256, G_SMEM>>>(w12);         // 3 (ncu slot)
    gemm2_kernel<<<dim3(8, 16, E), 256, G_SMEM>>>(w3);          // 4
    combine_kernel<<<(T * D / 4 + 255) / 256, 256>>>(out, out_size); // 5
}

// round 7
// speedup vs baseline: 1.0040x; 1.0040x over previous
#include <cuda_runtime.h>
#include <cuda_fp16.h>
#include <cstdint>
#include <math.h>

#define T 2048        // B*S tokens
#define D 1024
#define Hh 2048
#define E 8
#define TWOH 4096
#define NSLOT (T * 2)

// ---- scratch ----
__device__ int    g_cnt[E];
__device__ int    g_list[E][T];
__device__ float  g_wt[NSLOT];
__device__ __half g_xh[(size_t)T * D];            // fp16 x (4 MB)
__device__ __half g_hiddenh[(size_t)NSLOT * Hh];  // fp16 hidden (16 MB)
__device__ float  g_yslot[(size_t)NSLOT * D];     // 16 MB
__device__ float  g_aux;

// ======================= helpers =======================
__device__ __forceinline__ uint32_t smem_u32(const void* p) {
    uint32_t a;
    asm("{ .reg .u64 t; cvta.to.shared.u64 t, %1; cvt.u32.u64 %0, t; }" : "=r"(a) : "l"(p));
    return a;
}
__device__ __forceinline__ uint32_t h2u(__half2 h) { return *(uint32_t*)&h; }

#define CP_ASYNC16(dst, src) \
    asm volatile("cp.async.cg.shared.global [%0], [%1], 16;" :: "r"(dst), "l"(src))
#define CP_COMMIT() asm volatile("cp.async.commit_group;")
#define CP_WAIT0()  asm volatile("cp.async.wait_group 0;" ::: "memory")

__device__ __forceinline__ void ldsm4(uint32_t* r, uint32_t addr) {
    asm volatile("ldmatrix.sync.aligned.m8n8.x4.shared.b16 {%0,%1,%2,%3},[%4];"
        : "=r"(r[0]), "=r"(r[1]), "=r"(r[2]), "=r"(r[3]) : "r"(addr));
}
__device__ __forceinline__ void ldsm4t(uint32_t* r, uint32_t addr) {
    asm volatile("ldmatrix.sync.aligned.m8n8.x4.trans.shared.b16 {%0,%1,%2,%3},[%4];"
        : "=r"(r[0]), "=r"(r[1]), "=r"(r[2]), "=r"(r[3]) : "r"(addr));
}
__device__ __forceinline__ void mma16(float* c, const uint32_t* a, uint32_t b0, uint32_t b1) {
    asm volatile(
        "mma.sync.aligned.m16n8k16.row.col.f32.f16.f16.f32 "
        "{%0,%1,%2,%3},{%4,%5,%6,%7},{%8,%9},{%0,%1,%2,%3};"
        : "+f"(c[0]), "+f"(c[1]), "+f"(c[2]), "+f"(c[3])
        : "r"(a[0]), "r"(a[1]), "r"(a[2]), "r"(a[3]), "r"(b0), "r"(b1));
}

// ======================= small kernels =======================
__global__ void zero_kernel() {
    int i = threadIdx.x;
    if (i < E) g_cnt[i] = 0;
    if (i == 0) g_aux = 0.0f;
}

__global__ void prep_x(const float* __restrict__ x) {
    int i = blockIdx.x * blockDim.x + threadIdx.x;
    if (i < T * D / 4) {
        float4 v = ((const float4*)x)[i];
        uint2 u;
        u.x = h2u(__floats2half2_rn(v.x, v.y));
        u.y = h2u(__floats2half2_rn(v.z, v.w));
        ((uint2*)g_xh)[i] = u;
    }
}

__global__ void router_kernel(const float* __restrict__ x,
                              const float* __restrict__ rw,
                              const float* __restrict__ rb) {
    int warp = threadIdx.x >> 5;
    int lane = threadIdx.x & 31;
    int t = blockIdx.x * (blockDim.x >> 5) + warp;
    if (t >= T) return;

    const float* xr = x + (size_t)t * D;
    float acc[E];
#pragma unroll
    for (int e = 0; e < E; e++) acc[e] = 0.0f;
    for (int d = lane; d < D; d += 32) {
        float xv = xr[d];
#pragma unroll
        for (int e = 0; e < E; e++) acc[e] += xv * rw[e * D + d];
    }
#pragma unroll
    for (int e = 0; e < E; e++) {
#pragma unroll
        for (int off = 16; off; off >>= 1)
            acc[e] += __shfl_xor_sync(0xffffffffu, acc[e], off);
    }
    if (lane == 0) {
        float score[E];
        float auxl = 0.0f;
#pragma unroll
        for (int e = 0; e < E; e++) {
            float lg = acc[e] + rb[e];
            auxl += lg * lg;
            score[e] = 1.0f / (1.0f + expf(-lg));
        }
        int e0 = 0;
#pragma unroll
        for (int e = 1; e < E; e++) if (score[e] > score[e0]) e0 = e;
        int e1 = -1;
#pragma unroll
        for (int e = 0; e < E; e++) {
            if (e == e0) continue;
            if (e1 < 0 || score[e] > score[e1]) e1 = e;
        }
        float s0 = score[e0], s1 = score[e1];
        float inv = 1.0f / (s0 + s1 + 1e-6f);
        g_wt[2 * t]     = s0 * inv;
        g_wt[2 * t + 1] = s1 * inv;
        int p0 = atomicAdd(&g_cnt[e0], 1); g_list[e0][p0] = 2 * t;
        int p1 = atomicAdd(&g_cnt[e1], 1); g_list[e1][p1] = 2 * t + 1;
        atomicAdd(&g_aux, auxl);
    }
}

// combine + aux fused
__global__ void combine_kernel(float* __restrict__ out, int out_size) {
    int i = blockIdx.x * blockDim.x + threadIdx.x;
    if (i == 0 && out_size > T * D)
        out[T * D] = 0.01f * g_aux / (float)(T * E);
    const int total = T * D / 4;
    if (i >= total) return;
    int t = i / (D / 4);
    int j = i % (D / 4);
    float4 a = ((const float4*)(g_yslot + (size_t)(2 * t) * D))[j];
    float4 b = ((const float4*)(g_yslot + (size_t)(2 * t + 1) * D))[j];
    float4 o = {a.x + b.x, a.y + b.y, a.z + b.z, a.w + b.w};
    ((float4*)out)[i] = o;
}

// ======================= GEMM common layout =======================
// slot[256]@0, tok/src[256]@1024
// A: [m:256][k:64] fp16, row stride 144B. stage = 36864B
// B: [k:64][n:64+8pad] fp16, row stride 144B. stage = 9216B
#define A_OFF 2048
#define A_STG 36864
#define B_OFF (2048 + 2 * 36864)
#define B_STG 9216
#define G_SMEM (B_OFF + 2 * 9216)

// ======================= GEMM1 =======================
// 256m x 32n dual (W1 cols n0..n0+31 in B[:,0:32), W2 in B[:,32:64)).
// 8 warps, warp w owns rows [32w, 32w+32). KC=64, 16 chunks.
__global__ void __launch_bounds__(256, 2) gemm1_kernel(const float* __restrict__ w12) {
    int e = blockIdx.z;
    int cnt = g_cnt[e];
    int m0 = blockIdx.x * 256;
    if (m0 >= cnt) return;
    int n0 = blockIdx.y * 32;

    extern __shared__ char smem[];
    uint32_t sb = smem_u32(smem);
    int* slot = (int*)smem;
    int* tok  = (int*)(smem + 1024);
    int tid = threadIdx.x, wid = tid >> 5, lane = tid & 31;
    int g = lane >> 2, tg = lane & 3;
    int wm = wid * 32;
    int q = lane >> 3, r = lane & 7;

#pragma unroll
    for (int j = 0; j < 1; j++) {
        int m = m0 + tid;
        int s = g_list[e][(m < cnt) ? m : 0];
        slot[tid] = (m < cnt) ? s : -1;
        tok[tid]  = s >> 1;
    }
    __syncthreads();

    const float* wb0 = w12 + (size_t)e * D * TWOH;
    uint32_t aBase = sb + A_OFF + (uint32_t)((wm + (q & 1) * 8 + r) * 144 + (q >> 1) * 16);
    uint32_t bBase = sb + B_OFF + (uint32_t)(((q & 1) * 8 + r) * 144 + (q >> 1) * 16);

    float4 rbv[4];

    // ---- prologue ----
#pragma unroll
    for (int j = 0; j < 8; j++) {
        int c = tid + j * 256;
        int m = c >> 3, kq = c & 7;
        const __half* src = g_xh + (size_t)tok[m] * D + kq * 8;
        CP_ASYNC16(sb + A_OFF + m * 144 + kq * 16, src);
    }
    CP_COMMIT();
#pragma unroll
    for (int j = 0; j < 4; j++) {
        int c = tid + j * 256;
        int k = c >> 4, f4 = c & 15;
        int col = (f4 < 8) ? (n0 + f4 * 4) : (Hh + n0 + (f4 - 8) * 4);
        rbv[j] = *(const float4*)(wb0 + (size_t)k * TWOH + col);
    }
#pragma unroll
    for (int j = 0; j < 4; j++) {
        int c = tid + j * 256;
        int k = c >> 4, f4 = c & 15;
        int dcol = (f4 < 8) ? (f4 * 4) : (32 + (f4 - 8) * 4);
        uint2 u;
        u.x = h2u(__floats2half2_rn(rbv[j].x, rbv[j].y));
        u.y = h2u(__floats2half2_rn(rbv[j].z, rbv[j].w));
        *(uint2*)(smem + B_OFF + k * 144 + dcol * 2) = u;
    }
    CP_WAIT0();
    __syncthreads();

    float acc1[2][4][4] = {}, acc2[2][4][4] = {};

    for (int i = 0; i < 16; i++) {
        int cur = i & 1, nxt = cur ^ 1;
        if (i + 1 < 16) {
            int k0 = (i + 1) * 64;
#pragma unroll
            for (int j = 0; j < 8; j++) {
                int c = tid + j * 256;
                int m = c >> 3, kq = c & 7;
                const __half* src = g_xh + (size_t)tok[m] * D + k0 + kq * 8;
                CP_ASYNC16(sb + A_OFF + nxt * A_STG + m * 144 + kq * 16, src);
            }
            CP_COMMIT();
#pragma unroll
            for (int j = 0; j < 4; j++) {
                int c = tid + j * 256;
                int k = c >> 4, f4 = c & 15;
                int col = (f4 < 8) ? (n0 + f4 * 4) : (Hh + n0 + (f4 - 8) * 4);
                rbv[j] = *(const float4*)(wb0 + (size_t)(k0 + k) * TWOH + col);
            }
        }
        // compute on cur
        {
            uint32_t aA = aBase + cur * A_STG;
            uint32_t bA = bBase + cur * B_STG;
#pragma unroll
            for (int kt = 0; kt < 4; kt++) {
                uint32_t a[2][4];
                ldsm4(a[0], aA + kt * 32);
                ldsm4(a[1], aA + kt * 32 + 16 * 144);
                uint32_t b1[8], b2[8];
                uint32_t bk = bA + kt * (16 * 144);
                ldsm4t(b1 + 0, bk + 0);
                ldsm4t(b1 + 4, bk + 16 * 2);
                ldsm4t(b2 + 0, bk + 32 * 2);
                ldsm4t(b2 + 4, bk + 48 * 2);
#pragma unroll
                for (int nt = 0; nt < 4; nt++) {
#pragma unroll
                    for (int mt = 0; mt < 2; mt++) {
                        mma16(acc1[mt][nt], a[mt], b1[2 * nt], b1[2 * nt + 1]);
                        mma16(acc2[mt][nt], a[mt], b2[2 * nt], b2[2 * nt + 1]);
                    }
                }
            }
        }
        if (i + 1 < 16) {
#pragma unroll
            for (int j = 0; j < 4; j++) {
                int c = tid + j * 256;
                int k = c >> 4, f4 = c & 15;
                int dcol = (f4 < 8) ? (f4 * 4) : (32 + (f4 - 8) * 4);
                uint2 u;
                u.x = h2u(__floats2half2_rn(rbv[j].x, rbv[j].y));
                u.y = h2u(__floats2half2_rn(rbv[j].z, rbv[j].w));
                *(uint2*)(smem + B_OFF + nxt * B_STG + k * 144 + dcol * 2) = u;
            }
        }
        CP_WAIT0();
        __syncthreads();
    }

    // epilogue: swiglu fuse, store fp16 hidden
#pragma unroll
    for (int mt = 0; mt < 2; mt++) {
        int r0 = wm + mt * 16 + g;
        int s0 = slot[r0], s1 = slot[r0 + 8];
#pragma unroll
        for (int nt = 0; nt < 4; nt++) {
            int col = n0 + nt * 8 + tg * 2;
            if (s0 >= 0) {
                float h1a = acc1[mt][nt][0], h2a = acc2[mt][nt][0];
                float h1b = acc1[mt][nt][1], h2b = acc2[mt][nt][1];
                float oa = h2a * h1a / (1.0f + expf(-h1a));
                float ob = h2b * h1b / (1.0f + expf(-h1b));
                *(uint32_t*)(g_hiddenh + (size_t)s0 * Hh + col) = h2u(__floats2half2_rn(oa, ob));
            }
            if (s1 >= 0) {
                float h1a = acc1[mt][nt][2], h2a = acc2[mt][nt][2];
                float h1b = acc1[mt][nt][3], h2b = acc2[mt][nt][3];
                float oa = h2a * h1a / (1.0f + expf(-h1a));
                float ob = h2b * h1b / (1.0f + expf(-h1b));
                *(uint32_t*)(g_hiddenh + (size_t)s1 * Hh + col) = h2u(__floats2half2_rn(oa, ob));
            }
        }
    }
}

// ======================= GEMM2 =======================
// 256m x 64n. 8 warps, warp w owns rows [32w, 32w+32). KC=64, 32 chunks.
__global__ void __launch_bounds__(256, 2) gemm2_kernel(const float* __restrict__ w3) {
    int e = blockIdx.z;
    int cnt = g_cnt[e];
    int m0 = blockIdx.x * 256;
    if (m0 >= cnt) return;
    int n0 = blockIdx.y * 64;

    extern __shared__ char smem[];
    uint32_t sb = smem_u32(smem);
    int* slot = (int*)smem;
    int* srcs = (int*)(smem + 1024);
    int tid = threadIdx.x, wid = tid >> 5, lane = tid & 31;
    int g = lane >> 2, tg = lane & 3;
    int wm = wid * 32;
    int q = lane >> 3, r = lane & 7;

    {
        int m = m0 + tid;
        int s = g_list[e][(m < cnt) ? m : 0];
        slot[tid] = (m < cnt) ? s : -1;
        srcs[tid] = s;
    }
    __syncthreads();

    const float* wb0 = w3 + (size_t)e * Hh * D + n0;
    uint32_t aBase = sb + A_OFF + (uint32_t)((wm + (q & 1) * 8 + r) * 144 + (q >> 1) * 16);
    uint32_t bBase = sb + B_OFF + (uint32_t)(((q & 1) * 8 + r) * 144 + (q >> 1) * 16);

    float4 rbv[4];

#pragma unroll
    for (int j = 0; j < 8; j++) {
        int c = tid + j * 256;
        int m = c >> 3, kq = c & 7;
        const __half* src = g_hiddenh + (size_t)srcs[m] * Hh + kq * 8;
        CP_ASYNC16(sb + A_OFF + m * 144 + kq * 16, src);
    }
    CP_COMMIT();
#pragma unroll
    for (int j = 0; j < 4; j++) {
        int c = tid + j * 256;
        int k = c >> 4, f4 = c & 15;
        rbv[j] = *(const float4*)(wb0 + (size_t)k * D + f4 * 4);
    }
#pragma unroll
    for (int j = 0; j < 4; j++) {
        int c = tid + j * 256;
        int k = c >> 4, f4 = c & 15;
        uint2 u;
        u.x = h2u(__floats2half2_rn(rbv[j].x, rbv[j].y));
        u.y = h2u(__floats2half2_rn(rbv[j].z, rbv[j].w));
        *(uint2*)(smem + B_OFF + k * 144 + f4 * 8) = u;
    }
    CP_WAIT0();
    __syncthreads();

    float acc[2][8][4] = {};

    for (int i = 0; i < 32; i++) {
        int cur = i & 1, nxt = cur ^ 1;
        if (i + 1 < 32) {
            int k0 = (i + 1) * 64;
#pragma unroll
            for (int j = 0; j < 8; j++) {
                int c = tid + j * 256;
                int m = c >> 3, kq = c & 7;
                const __half* src = g_hiddenh + (size_t)srcs[m] * Hh + k0 + kq * 8;
                CP_ASYNC16(sb + A_OFF + nxt * A_STG + m * 144 + kq * 16, src);
            }
            CP_COMMIT();
#pragma unroll
            for (int j = 0; j < 4; j++) {
                int c = tid + j * 256;
                int k = c >> 4, f4 = c & 15;
                rbv[j] = *(const float4*)(wb0 + (size_t)(k0 + k) * D + f4 * 4);
            }
        }
        {
            uint32_t aA = aBase + cur * A_STG;
            uint32_t bA = bBase + cur * B_STG;
#pragma unroll
            for (int kt = 0; kt < 4; kt++) {
                uint32_t a[2][4];
                ldsm4(a[0], aA + kt * 32);
                ldsm4(a[1], aA + kt * 32 + 16 * 144);
                uint32_t b[16];
                uint32_t bk = bA + kt * (16 * 144);
                ldsm4t(b + 0,  bk + 0);
                ldsm4t(b + 4,  bk + 16 * 2);
                ldsm4t(b + 8,  bk + 32 * 2);
                ldsm4t(b + 12, bk + 48 * 2);
#pragma unroll
                for (int nt = 0; nt < 8; nt++) {
#pragma unroll
                    for (int mt = 0; mt < 2; mt++)
                        mma16(acc[mt][nt], a[mt], b[2 * nt], b[2 * nt + 1]);
                }
            }
        }
        if (i + 1 < 32) {
#pragma unroll
            for (int j = 0; j < 4; j++) {
                int c = tid + j * 256;
                int k = c >> 4, f4 = c & 15;
                uint2 u;
                u.x = h2u(__floats2half2_rn(rbv[j].x, rbv[j].y));
                u.y = h2u(__floats2half2_rn(rbv[j].z, rbv[j].w));
                *(uint2*)(smem + B_OFF + nxt * B_STG + k * 144 + f4 * 8) = u;
            }
        }
        CP_WAIT0();
        __syncthreads();
    }

#pragma unroll
    for (int mt = 0; mt < 2; mt++) {
        int r0 = wm + mt * 16 + g;
        int s0 = slot[r0], s1 = slot[r0 + 8];
        float w0 = (s0 >= 0) ? g_wt[s0] : 0.0f;
        float w1 = (s1 >= 0) ? g_wt[s1] : 0.0f;
#pragma unroll
        for (int nt = 0; nt < 8; nt++) {
            int col = n0 + nt * 8 + tg * 2;
            if (s0 >= 0) {
                float2 v = {w0 * acc[mt][nt][0], w0 * acc[mt][nt][1]};
                *(float2*)(g_yslot + (size_t)s0 * D + col) = v;
            }
            if (s1 >= 0) {
                float2 v = {w1 * acc[mt][nt][2], w1 * acc[mt][nt][3]};
                *(float2*)(g_yslot + (size_t)s1 * D + col) = v;
            }
        }
    }
}

// ======================= launch =======================
extern "C" void kernel_launch(void* const* d_in, const int* in_sizes, int n_in,
                              void* d_out, int out_size) {
    const float* x   = (const float*)d_in[0];
    const float* rw  = (const float*)d_in[1];
    const float* rb  = (const float*)d_in[2];
    const float* w12 = (const float*)d_in[3];
    const float* w3  = (const float*)d_in[4];
    float* out = (float*)d_out;

    cudaFuncSetAttribute(gemm1_kernel, cudaFuncAttributeMaxDynamicSharedMemorySize, G_SMEM);
    cudaFuncSetAttribute(gemm2_kernel, cudaFuncAttributeMaxDynamicSharedMemorySize, G_SMEM);

    zero_kernel<<<1, 32>>>();                                   // 0
    prep_x<<<(T * D / 4 + 255) / 256, 256>>>(x);                // 1
    router_kernel<<<T / 8, 256>>>(x, rw, rb);                   // 2
    gemm1_kernel<<<dim3(8, 64, E), 256, G_SMEM>>>(w12);         // 3 (ncu slot)
    gemm2_kernel<<<dim3(8, 16, E), 256, G_SMEM>>>(w3);          // 4
    combine_kernel<<<(T * D / 4 + 255) / 256, 256>>>(out, out_size); // 5
}

// round 8
// speedup vs baseline: 1.3531x; 1.3477x over previous
#include <cuda_runtime.h>
#include <cuda_fp16.h>
#include <cstdint>
#include <math.h>

#define T 2048        // B*S tokens
#define D 1024
#define Hh 2048
#define E 8
#define TWOH 4096
#define NSLOT (T * 2)

// ---- scratch ----
__device__ int    g_cnt[E];
__device__ int    g_list[E][T];
__device__ float  g_wt[NSLOT];
__device__ __half g_xh[(size_t)T * D];             // fp16 x (4 MB)
__device__ __half g_w12h[(size_t)E * D * TWOH];    // fp16 w12 (64 MB)
__device__ __half g_w3h[(size_t)E * Hh * D];       // fp16 w3 (32 MB)
__device__ __half g_hiddenh[(size_t)NSLOT * Hh];   // fp16 hidden (16 MB)
__device__ float  g_yslot[(size_t)NSLOT * D];      // 16 MB
__device__ float  g_aux;

// ======================= helpers =======================
__device__ __forceinline__ uint32_t smem_u32(const void* p) {
    uint32_t a;
    asm("{ .reg .u64 t; cvta.to.shared.u64 t, %1; cvt.u32.u64 %0, t; }" : "=r"(a) : "l"(p));
    return a;
}
__device__ __forceinline__ uint32_t h2u(__half2 h) { return *(uint32_t*)&h; }

#define CP_ASYNC16(dst, src) \
    asm volatile("cp.async.cg.shared.global [%0], [%1], 16;" :: "r"(dst), "l"(src))
#define CP_COMMIT() asm volatile("cp.async.commit_group;")
#define CP_WAIT0()  asm volatile("cp.async.wait_group 0;" ::: "memory")

__device__ __forceinline__ void ldsm4(uint32_t* r, uint32_t addr) {
    asm volatile("ldmatrix.sync.aligned.m8n8.x4.shared.b16 {%0,%1,%2,%3},[%4];"
        : "=r"(r[0]), "=r"(r[1]), "=r"(r[2]), "=r"(r[3]) : "r"(addr));
}
__device__ __forceinline__ void ldsm4t(uint32_t* r, uint32_t addr) {
    asm volatile("ldmatrix.sync.aligned.m8n8.x4.trans.shared.b16 {%0,%1,%2,%3},[%4];"
        : "=r"(r[0]), "=r"(r[1]), "=r"(r[2]), "=r"(r[3]) : "r"(addr));
}
__device__ __forceinline__ void mma16(float* c, const uint32_t* a, uint32_t b0, uint32_t b1) {
    asm volatile(
        "mma.sync.aligned.m16n8k16.row.col.f32.f16.f16.f32 "
        "{%0,%1,%2,%3},{%4,%5,%6,%7},{%8,%9},{%0,%1,%2,%3};"
        : "+f"(c[0]), "+f"(c[1]), "+f"(c[2]), "+f"(c[3])
        : "r"(a[0]), "r"(a[1]), "r"(a[2]), "r"(a[3]), "r"(b0), "r"(b1));
}

// ======================= small kernels =======================
__global__ void zero_kernel() {
    int i = threadIdx.x;
    if (i < E) g_cnt[i] = 0;
    if (i == 0) g_aux = 0.0f;
}

// router + x->fp16 conversion fused (one warp per token)
__global__ void router_kernel(const float* __restrict__ x,
                              const float* __restrict__ rw,
                              const float* __restrict__ rb) {
    int warp = threadIdx.x >> 5;
    int lane = threadIdx.x & 31;
    int t = blockIdx.x * (blockDim.x >> 5) + warp;
    if (t >= T) return;

    const float2* xr = (const float2*)(x + (size_t)t * D);
    uint32_t* xo = (uint32_t*)(g_xh + (size_t)t * D);
    float acc[E];
#pragma unroll
    for (int e = 0; e < E; e++) acc[e] = 0.0f;
#pragma unroll 4
    for (int p = lane; p < D / 2; p += 32) {
        float2 v = xr[p];
        xo[p] = h2u(__floats2half2_rn(v.x, v.y));
#pragma unroll
        for (int e = 0; e < E; e++)
            acc[e] += v.x * rw[e * D + 2 * p] + v.y * rw[e * D + 2 * p + 1];
    }
#pragma unroll
    for (int e = 0; e < E; e++) {
#pragma unroll
        for (int off = 16; off; off >>= 1)
            acc[e] += __shfl_xor_sync(0xffffffffu, acc[e], off);
    }
    if (lane == 0) {
        float score[E];
        float auxl = 0.0f;
#pragma unroll
        for (int e = 0; e < E; e++) {
            float lg = acc[e] + rb[e];
            auxl += lg * lg;
            score[e] = 1.0f / (1.0f + expf(-lg));
        }
        int e0 = 0;
#pragma unroll
        for (int e = 1; e < E; e++) if (score[e] > score[e0]) e0 = e;
        int e1 = -1;
#pragma unroll
        for (int e = 0; e < E; e++) {
            if (e == e0) continue;
            if (e1 < 0 || score[e] > score[e1]) e1 = e;
        }
        float s0 = score[e0], s1 = score[e1];
        float inv = 1.0f / (s0 + s1 + 1e-6f);
        g_wt[2 * t]     = s0 * inv;
        g_wt[2 * t + 1] = s1 * inv;
        int p0 = atomicAdd(&g_cnt[e0], 1); g_list[e0][p0] = 2 * t;
        int p1 = atomicAdd(&g_cnt[e1], 1); g_list[e1][p1] = 2 * t + 1;
        atomicAdd(&g_aux, auxl);
    }
}

// weight fp32 -> fp16 conversion (grid-stride over float4)
__global__ void prep_w12(const float* __restrict__ w) {
    const int total = E * D * TWOH / 4;
    for (int i = blockIdx.x * blockDim.x + threadIdx.x; i < total; i += gridDim.x * blockDim.x) {
        float4 v = ((const float4*)w)[i];
        uint2 u;
        u.x = h2u(__floats2half2_rn(v.x, v.y));
        u.y = h2u(__floats2half2_rn(v.z, v.w));
        ((uint2*)g_w12h)[i] = u;
    }
}
__global__ void prep_w3(const float* __restrict__ w) {
    const int total = E * Hh * D / 4;
    for (int i = blockIdx.x * blockDim.x + threadIdx.x; i < total; i += gridDim.x * blockDim.x) {
        float4 v = ((const float4*)w)[i];
        uint2 u;
        u.x = h2u(__floats2half2_rn(v.x, v.y));
        u.y = h2u(__floats2half2_rn(v.z, v.w));
        ((uint2*)g_w3h)[i] = u;
    }
}

// combine + aux fused
__global__ void combine_kernel(float* __restrict__ out, int out_size) {
    int i = blockIdx.x * blockDim.x + threadIdx.x;
    if (i == 0 && out_size > T * D)
        out[T * D] = 0.01f * g_aux / (float)(T * E);
    const int total = T * D / 4;
    if (i >= total) return;
    int t = i / (D / 4);
    int j = i % (D / 4);
    float4 a = ((const float4*)(g_yslot + (size_t)(2 * t) * D))[j];
    float4 b = ((const float4*)(g_yslot + (size_t)(2 * t + 1) * D))[j];
    float4 o = {a.x + b.x, a.y + b.y, a.z + b.z, a.w + b.w};
    ((float4*)out)[i] = o;
}

// ======================= GEMM common layout =======================
// slot[128]@0, tok/src[128]@512
// A: [m:128][k:64] fp16, row stride 144B. stage = 18432B
// B: [k:64][n:128] fp16, row stride 272B. stage = 17408B
#define A_OFF 1024
#define A_STG 18432
#define B_OFF (1024 + 2 * 18432)
#define B_STG 17408
#define G_SMEM (B_OFF + 2 * 17408)

// ======================= GEMM1 =======================
// hidden[slot, n] = silu(xh@W1)[n] * (xh@W2)[n]. CTA 128m x 64n dual. KC=64, 16 chunks.
// B smem cols 0..63 = W1 cols n0.., cols 64..127 = W2 cols n0..
__global__ void __launch_bounds__(256, 2) gemm1_kernel() {
    int e = blockIdx.z;
    int cnt = g_cnt[e];
    int m0 = blockIdx.x * 128;
    if (m0 >= cnt) return;
    int n0 = blockIdx.y * 64;

    extern __shared__ char smem[];
    uint32_t sb = smem_u32(smem);
    int* slot = (int*)smem;
    int* tok  = (int*)(smem + 512);
    int tid = threadIdx.x, wid = tid >> 5, lane = tid & 31;
    int g = lane >> 2, tg = lane & 3;
    int wm = (wid & 3) * 32, wn = (wid >> 2) * 32;
    int q = lane >> 3, r = lane & 7;

    if (tid < 128) {
        int m = m0 + tid;
        int s = g_list[e][(m < cnt) ? m : 0];
        slot[tid] = (m < cnt) ? s : -1;
        tok[tid]  = s >> 1;
    }
    __syncthreads();

    const __half* wb0 = g_w12h + (size_t)e * D * TWOH;
    uint32_t aBase = sb + A_OFF + (uint32_t)((wm + (q & 1) * 8 + r) * 144 + (q >> 1) * 16);
    uint32_t bBase = sb + B_OFF + (uint32_t)(((q & 1) * 8 + r) * 272 + (q >> 1) * 16);

    // per-thread load coords
    int amr = tid >> 1;              // A: also used via c-loop below
    (void)amr;

    // ---- prologue: A(0)+B(0) cp.async ----
#pragma unroll
    for (int j = 0; j < 2; j++) {
        int c = tid + j * 256;
        int m = c >> 2, kq = c & 3;  // 128 rows x 4 x 16B (64 halfs)
        const __half* src = g_xh + (size_t)tok[m] * D + kq * 16;
        CP_ASYNC16(sb + A_OFF + m * 144 + kq * 32, src);
        CP_ASYNC16(sb + A_OFF + m * 144 + kq * 32 + 16, src + 8);
    }
#pragma unroll
    for (int j = 0; j < 4; j++) {
        int c = tid + j * 256;
        int k = c >> 4, seg = c & 15;  // 64 rows x 16 x 16B
        int scol = (seg < 8) ? (n0 + seg * 8) : (Hh + n0 + (seg - 8) * 8);
        CP_ASYNC16(sb + B_OFF + k * 272 + seg * 16, wb0 + (size_t)k * TWOH + scol);
    }
    CP_COMMIT();
    CP_WAIT0();
    __syncthreads();

    float acc1[2][4][4] = {}, acc2[2][4][4] = {};

    for (int i = 0; i < 16; i++) {
        int cur = i & 1, nxt = cur ^ 1;
        if (i + 1 < 16) {
            int k0 = (i + 1) * 64;
#pragma unroll
            for (int j = 0; j < 2; j++) {
                int c = tid + j * 256;
                int m = c >> 2, kq = c & 3;
                const __half* src = g_xh + (size_t)tok[m] * D + k0 + kq * 16;
                CP_ASYNC16(sb + A_OFF + nxt * A_STG + m * 144 + kq * 32, src);
                CP_ASYNC16(sb + A_OFF + nxt * A_STG + m * 144 + kq * 32 + 16, src + 8);
            }
#pragma unroll
            for (int j = 0; j < 4; j++) {
                int c = tid + j * 256;
                int k = c >> 4, seg = c & 15;
                int scol = (seg < 8) ? (n0 + seg * 8) : (Hh + n0 + (seg - 8) * 8);
                CP_ASYNC16(sb + B_OFF + nxt * B_STG + k * 272 + seg * 16,
                           wb0 + (size_t)(k0 + k) * TWOH + scol);
            }
            CP_COMMIT();
        }
        // compute on cur
        {
            uint32_t aA = aBase + cur * A_STG;
            uint32_t bA = bBase + cur * B_STG;
#pragma unroll
            for (int kt = 0; kt < 4; kt++) {
                uint32_t a[2][4];
                ldsm4(a[0], aA + kt * 32);
                ldsm4(a[1], aA + kt * 32 + 16 * 144);
                uint32_t b1[8], b2[8];
                uint32_t bk = bA + kt * (16 * 272);
                ldsm4t(b1 + 0, bk + (wn + 0) * 2);
                ldsm4t(b1 + 4, bk + (wn + 16) * 2);
                ldsm4t(b2 + 0, bk + (64 + wn) * 2);
                ldsm4t(b2 + 4, bk + (64 + wn + 16) * 2);
#pragma unroll
                for (int nt = 0; nt < 4; nt++) {
#pragma unroll
                    for (int mt = 0; mt < 2; mt++) {
                        mma16(acc1[mt][nt], a[mt], b1[2 * nt], b1[2 * nt + 1]);
                        mma16(acc2[mt][nt], a[mt], b2[2 * nt], b2[2 * nt + 1]);
                    }
                }
            }
        }
        CP_WAIT0();
        __syncthreads();
    }

    // epilogue: swiglu fuse, store fp16 hidden
#pragma unroll
    for (int mt = 0; mt < 2; mt++) {
        int r0 = wm + mt * 16 + g;
        int s0 = slot[r0], s1 = slot[r0 + 8];
#pragma unroll
        for (int nt = 0; nt < 4; nt++) {
            int col = n0 + wn + nt * 8 + tg * 2;
            if (s0 >= 0) {
                float h1a = acc1[mt][nt][0], h2a = acc2[mt][nt][0];
                float h1b = acc1[mt][nt][1], h2b = acc2[mt][nt][1];
                float oa = h2a * h1a / (1.0f + expf(-h1a));
                float ob = h2b * h1b / (1.0f + expf(-h1b));
                *(uint32_t*)(g_hiddenh + (size_t)s0 * Hh + col) = h2u(__floats2half2_rn(oa, ob));
            }
            if (s1 >= 0) {
                float h1a = acc1[mt][nt][2], h2a = acc2[mt][nt][2];
                float h1b = acc1[mt][nt][3], h2b = acc2[mt][nt][3];
                float oa = h2a * h1a / (1.0f + expf(-h1a));
                float ob = h2b * h1b / (1.0f + expf(-h1b));
                *(uint32_t*)(g_hiddenh + (size_t)s1 * Hh + col) = h2u(__floats2half2_rn(oa, ob));
            }
        }
    }
}

// ======================= GEMM2 =======================
// yslot[slot, n] = wt[slot] * (hiddenh @ w3h)[n]. CTA 128m x 128n. KC=64, 32 chunks.
__global__ void __launch_bounds__(256, 2) gemm2_kernel() {
    int e = blockIdx.z;
    int cnt = g_cnt[e];
    int m0 = blockIdx.x * 128;
    if (m0 >= cnt) return;
    int n0 = blockIdx.y * 128;

    extern __shared__ char smem[];
    uint32_t sb = smem_u32(smem);
    int* slot = (int*)smem;
    int* srcs = (int*)(smem + 512);
    int tid = threadIdx.x, wid = tid >> 5, lane = tid & 31;
    int g = lane >> 2, tg = lane & 3;
    int wm = (wid & 3) * 32, wn = (wid >> 2) * 64;
    int q = lane >> 3, r = lane & 7;

    if (tid < 128) {
        int m = m0 + tid;
        int s = g_list[e][(m < cnt) ? m : 0];
        slot[tid] = (m < cnt) ? s : -1;
        srcs[tid] = s;
    }
    __syncthreads();

    const __half* wb0 = g_w3h + (size_t)e * Hh * D + n0;
    uint32_t aBase = sb + A_OFF + (uint32_t)((wm + (q & 1) * 8 + r) * 144 + (q >> 1) * 16);
    uint32_t bBase = sb + B_OFF + (uint32_t)(((q & 1) * 8 + r) * 272 + (q >> 1) * 16);

#pragma unroll
    for (int j = 0; j < 2; j++) {
        int c = tid + j * 256;
        int m = c >> 2, kq = c & 3;
        const __half* src = g_hiddenh + (size_t)srcs[m] * Hh + kq * 16;
        CP_ASYNC16(sb + A_OFF + m * 144 + kq * 32, src);
        CP_ASYNC16(sb + A_OFF + m * 144 + kq * 32 + 16, src + 8);
    }
#pragma unroll
    for (int j = 0; j < 4; j++) {
        int c = tid + j * 256;
        int k = c >> 4, seg = c & 15;
        CP_ASYNC16(sb + B_OFF + k * 272 + seg * 16, wb0 + (size_t)k * D + seg * 8);
    }
    CP_COMMIT();
    CP_WAIT0();
    __syncthreads();

    float acc[2][8][4] = {};

    for (int i = 0; i < 32; i++) {
        int cur = i & 1, nxt = cur ^ 1;
        if (i + 1 < 32) {
            int k0 = (i + 1) * 64;
#pragma unroll
            for (int j = 0; j < 2; j++) {
                int c = tid + j * 256;
                int m = c >> 2, kq = c & 3;
                const __half* src = g_hiddenh + (size_t)srcs[m] * Hh + k0 + kq * 16;
                CP_ASYNC16(sb + A_OFF + nxt * A_STG + m * 144 + kq * 32, src);
                CP_ASYNC16(sb + A_OFF + nxt * A_STG + m * 144 + kq * 32 + 16, src + 8);
            }
#pragma unroll
            for (int j = 0; j < 4; j++) {
                int c = tid + j * 256;
                int k = c >> 4, seg = c & 15;
                CP_ASYNC16(sb + B_OFF + nxt * B_STG + k * 272 + seg * 16,
                           wb0 + (size_t)(k0 + k) * D + seg * 8);
            }
            CP_COMMIT();
        }
        {
            uint32_t aA = aBase + cur * A_STG;
            uint32_t bA = bBase + cur * B_STG;
#pragma unroll
            for (int kt = 0; kt < 4; kt++) {
                uint32_t a[2][4];
                ldsm4(a[0], aA + kt * 32);
                ldsm4(a[1], aA + kt * 32 + 16 * 144);
                uint32_t b[16];
                uint32_t bk = bA + kt * (16 * 272);
                ldsm4t(b + 0,  bk + (wn + 0) * 2);
                ldsm4t(b + 4,  bk + (wn + 16) * 2);
                ldsm4t(b + 8,  bk + (wn + 32) * 2);
                ldsm4t(b + 12, bk + (wn + 48) * 2);
#pragma unroll
                for (int nt = 0; nt < 8; nt++) {
#pragma unroll
                    for (int mt = 0; mt < 2; mt++)
                        mma16(acc[mt][nt], a[mt], b[2 * nt], b[2 * nt + 1]);
                }
            }
        }
        CP_WAIT0();
        __syncthreads();
    }

#pragma unroll
    for (int mt = 0; mt < 2; mt++) {
        int r0 = wm + mt * 16 + g;
        int s0 = slot[r0], s1 = slot[r0 + 8];
        float w0 = (s0 >= 0) ? g_wt[s0] : 0.0f;
        float w1 = (s1 >= 0) ? g_wt[s1] : 0.0f;
#pragma unroll
        for (int nt = 0; nt < 8; nt++) {
            int col = n0 + wn + nt * 8 + tg * 2;
            if (s0 >= 0) {
                float2 v = {w0 * acc[mt][nt][0], w0 * acc[mt][nt][1]};
                *(float2*)(g_yslot + (size_t)s0 * D + col) = v;
            }
            if (s1 >= 0) {
                float2 v = {w1 * acc[mt][nt][2], w1 * acc[mt][nt][3]};
                *(float2*)(g_yslot + (size_t)s1 * D + col) = v;
            }
        }
    }
}

// ======================= launch =======================
extern "C" void kernel_launch(void* const* d_in, const int* in_sizes, int n_in,
                              void* d_out, int out_size) {
    const float* x   = (const float*)d_in[0];
    const float* rw  = (const float*)d_in[1];
    const float* rb  = (const float*)d_in[2];
    const float* w12 = (const float*)d_in[3];
    const float* w3  = (const float*)d_in[4];
    float* out = (float*)d_out;

    cudaFuncSetAttribute(gemm1_kernel, cudaFuncAttributeMaxDynamicSharedMemorySize, G_SMEM);
    cudaFuncSetAttribute(gemm2_kernel, cudaFuncAttributeMaxDynamicSharedMemorySize, G_SMEM);

    zero_kernel<<<1, 32>>>();                                        // 0
    router_kernel<<<T / 8, 256>>>(x, rw, rb);                        // 1 (also x->fp16)
    prep_w12<<<2048, 256>>>(w12);                                    // 2
    gemm1_kernel<<<dim3(16, 32, E), 256, G_SMEM>>>();                // 3 (ncu slot)
    prep_w3<<<1024, 256>>>(w3);                                      // 4
    gemm2_kernel<<<dim3(16, 8, E), 256, G_SMEM>>>();                 // 5
    combine_kernel<<<(T * D / 4 + 255) / 256, 256>>>(out, out_size); // 6
}

// round 9
// speedup vs baseline: 1.6045x; 1.1858x over previous
#include <cuda_runtime.h>
#include <cuda_fp16.h>
#include <cstdint>
#include <math.h>

#define T 2048        // B*S tokens
#define D 1024
#define Hh 2048
#define E 8
#define TWOH 4096
#define NSLOT (T * 2)

// ---- scratch ----
__device__ int    g_cnt[E];
__device__ int    g_list[E][T];
__device__ float  g_wt[NSLOT];
__device__ __half g_xh[(size_t)T * D];            // fp16 x (4 MB)
__device__ __half g_hiddenh[(size_t)NSLOT * Hh];  // fp16 hidden (16 MB)
__device__ float  g_aux;

// ======================= helpers =======================
__device__ __forceinline__ uint32_t smem_u32(const void* p) {
    uint32_t a;
    asm("{ .reg .u64 t; cvta.to.shared.u64 t, %1; cvt.u32.u64 %0, t; }" : "=r"(a) : "l"(p));
    return a;
}
__device__ __forceinline__ uint32_t h2u(__half2 h) { return *(uint32_t*)&h; }

#define CP_ASYNC16(dst, src) \
    asm volatile("cp.async.cg.shared.global [%0], [%1], 16;" :: "r"(dst), "l"(src))
#define CP_COMMIT() asm volatile("cp.async.commit_group;")
#define CP_WAIT0()  asm volatile("cp.async.wait_group 0;" ::: "memory")

__device__ __forceinline__ void ldsm4(uint32_t* r, uint32_t addr) {
    asm volatile("ldmatrix.sync.aligned.m8n8.x4.shared.b16 {%0,%1,%2,%3},[%4];"
        : "=r"(r[0]), "=r"(r[1]), "=r"(r[2]), "=r"(r[3]) : "r"(addr));
}
__device__ __forceinline__ void ldsm4t(uint32_t* r, uint32_t addr) {
    asm volatile("ldmatrix.sync.aligned.m8n8.x4.trans.shared.b16 {%0,%1,%2,%3},[%4];"
        : "=r"(r[0]), "=r"(r[1]), "=r"(r[2]), "=r"(r[3]) : "r"(addr));
}
__device__ __forceinline__ void mma16(float* c, const uint32_t* a, uint32_t b0, uint32_t b1) {
    asm volatile(
        "mma.sync.aligned.m16n8k16.row.col.f32.f16.f16.f32 "
        "{%0,%1,%2,%3},{%4,%5,%6,%7},{%8,%9},{%0,%1,%2,%3};"
        : "+f"(c[0]), "+f"(c[1]), "+f"(c[2]), "+f"(c[3])
        : "r"(a[0]), "r"(a[1]), "r"(a[2]), "r"(a[3]), "r"(b0), "r"(b1));
}

// ======================= small kernels =======================
__global__ void zero_kernel() {
    int i = threadIdx.x;
    if (i < E) g_cnt[i] = 0;
    if (i == 0) g_aux = 0.0f;
}

// zero the T*D output region (atomic accumulation target)
__global__ void zero_out(float* __restrict__ out) {
    int i = blockIdx.x * blockDim.x + threadIdx.x;
    if (i < T * D / 4) ((float4*)out)[i] = make_float4(0.f, 0.f, 0.f, 0.f);
}

// router + x->fp16 conversion fused (one warp per token)
__global__ void router_kernel(const float* __restrict__ x,
                              const float* __restrict__ rw,
                              const float* __restrict__ rb) {
    int warp = threadIdx.x >> 5;
    int lane = threadIdx.x & 31;
    int t = blockIdx.x * (blockDim.x >> 5) + warp;
    if (t >= T) return;

    const float2* xr = (const float2*)(x + (size_t)t * D);
    uint32_t* xo = (uint32_t*)(g_xh + (size_t)t * D);
    float acc[E];
#pragma unroll
    for (int e = 0; e < E; e++) acc[e] = 0.0f;
#pragma unroll 4
    for (int p = lane; p < D / 2; p += 32) {
        float2 v = xr[p];
        xo[p] = h2u(__floats2half2_rn(v.x, v.y));
#pragma unroll
        for (int e = 0; e < E; e++)
            acc[e] += v.x * rw[e * D + 2 * p] + v.y * rw[e * D + 2 * p + 1];
    }
#pragma unroll
    for (int e = 0; e < E; e++) {
#pragma unroll
        for (int off = 16; off; off >>= 1)
            acc[e] += __shfl_xor_sync(0xffffffffu, acc[e], off);
    }
    if (lane == 0) {
        float score[E];
        float auxl = 0.0f;
#pragma unroll
        for (int e = 0; e < E; e++) {
            float lg = acc[e] + rb[e];
            auxl += lg * lg;
            score[e] = 1.0f / (1.0f + expf(-lg));
        }
        int e0 = 0;
#pragma unroll
        for (int e = 1; e < E; e++) if (score[e] > score[e0]) e0 = e;
        int e1 = -1;
#pragma unroll
        for (int e = 0; e < E; e++) {
            if (e == e0) continue;
            if (e1 < 0 || score[e] > score[e1]) e1 = e;
        }
        float s0 = score[e0], s1 = score[e1];
        float inv = 1.0f / (s0 + s1 + 1e-6f);
        g_wt[2 * t]     = s0 * inv;
        g_wt[2 * t + 1] = s1 * inv;
        int p0 = atomicAdd(&g_cnt[e0], 1); g_list[e0][p0] = 2 * t;
        int p1 = atomicAdd(&g_cnt[e1], 1); g_list[e1][p1] = 2 * t + 1;
        atomicAdd(&g_aux, auxl);
    }
}

// ======================= GEMM common layout =======================
// slot[128]@0, tok/src[128]@512
// A: [m:128][k:64] fp16, row stride 144B. stage = 18432B
// B: [k:64][n:128] fp16, row stride 272B. stage = 17408B
#define A_OFF 1024
#define A_STG 18432
#define B_OFF (1024 + 2 * 18432)
#define B_STG 17408
#define G_SMEM (B_OFF + 2 * 17408)

// ======================= GEMM1 =======================
// hidden[slot, n] = silu(xh@W1)[n] * (xh@W2)[n]. CTA 128m x 64n dual. KC=64, 16 chunks.
__global__ void __launch_bounds__(256, 2) gemm1_kernel(const float* __restrict__ w12) {
    int e = blockIdx.z;
    int cnt = g_cnt[e];
    int m0 = blockIdx.x * 128;
    if (m0 >= cnt) return;
    int n0 = blockIdx.y * 64;

    extern __shared__ char smem[];
    uint32_t sb = smem_u32(smem);
    int* slot = (int*)smem;
    int* tok  = (int*)(smem + 512);
    int tid = threadIdx.x, wid = tid >> 5, lane = tid & 31;
    int g = lane >> 2, tg = lane & 3;
    int wm = (wid & 3) * 32, wn = (wid >> 2) * 32;
    int q = lane >> 3, r = lane & 7;

    if (tid < 128) {
        int m = m0 + tid;
        int s = g_list[e][(m < cnt) ? m : 0];
        slot[tid] = (m < cnt) ? s : -1;
        tok[tid]  = s >> 1;
    }
    __syncthreads();

    const float* wb0 = w12 + (size_t)e * D * TWOH;
    uint32_t aBase = sb + A_OFF + (uint32_t)((wm + (q & 1) * 8 + r) * 144 + (q >> 1) * 16);
    uint32_t bBase = sb + B_OFF + (uint32_t)(((q & 1) * 8 + r) * 272 + (q >> 1) * 16);

    float4 rbv[8];

    // ---- prologue: A(0) cp.async, B(0) reg-stage ----
#pragma unroll
    for (int j = 0; j < 4; j++) {
        int c = tid + j * 256;
        int m = c >> 3, kq = c & 7;
        const __half* src = g_xh + (size_t)tok[m] * D + kq * 8;
        CP_ASYNC16(sb + A_OFF + m * 144 + kq * 16, src);
    }
    CP_COMMIT();
#pragma unroll
    for (int j = 0; j < 8; j++) {
        int c = tid + j * 256;
        int k = c >> 5, n4 = c & 31;
        int col = (n4 < 16) ? (n0 + n4 * 4) : (Hh + n0 + (n4 - 16) * 4);
        rbv[j] = *(const float4*)(wb0 + (size_t)k * TWOH + col);
    }
#pragma unroll
    for (int j = 0; j < 8; j++) {
        int c = tid + j * 256;
        int k = c >> 5, n4 = c & 31;
        uint2 u;
        u.x = h2u(__floats2half2_rn(rbv[j].x, rbv[j].y));
        u.y = h2u(__floats2half2_rn(rbv[j].z, rbv[j].w));
        *(uint2*)(smem + B_OFF + k * 272 + n4 * 8) = u;
    }
    CP_WAIT0();
    __syncthreads();

    float acc1[2][4][4] = {}, acc2[2][4][4] = {};

    for (int i = 0; i < 16; i++) {
        int cur = i & 1, nxt = cur ^ 1;
        if (i + 1 < 16) {
            int k0 = (i + 1) * 64;
#pragma unroll
            for (int j = 0; j < 4; j++) {
                int c = tid + j * 256;
                int m = c >> 3, kq = c & 7;
                const __half* src = g_xh + (size_t)tok[m] * D + k0 + kq * 8;
                CP_ASYNC16(sb + A_OFF + nxt * A_STG + m * 144 + kq * 16, src);
            }
            CP_COMMIT();
#pragma unroll
            for (int j = 0; j < 8; j++) {
                int c = tid + j * 256;
                int k = c >> 5, n4 = c & 31;
                int col = (n4 < 16) ? (n0 + n4 * 4) : (Hh + n0 + (n4 - 16) * 4);
                rbv[j] = *(const float4*)(wb0 + (size_t)(k0 + k) * TWOH + col);
            }
        }
        // compute on cur
        {
            uint32_t aA = aBase + cur * A_STG;
            uint32_t bA = bBase + cur * B_STG;
#pragma unroll
            for (int kt = 0; kt < 4; kt++) {
                uint32_t a[2][4];
                ldsm4(a[0], aA + kt * 32);
                ldsm4(a[1], aA + kt * 32 + 16 * 144);
                uint32_t b1[8], b2[8];
                uint32_t bk = bA + kt * (16 * 272);
                ldsm4t(b1 + 0, bk + (wn + 0) * 2);
                ldsm4t(b1 + 4, bk + (wn + 16) * 2);
                ldsm4t(b2 + 0, bk + (64 + wn) * 2);
                ldsm4t(b2 + 4, bk + (64 + wn + 16) * 2);
#pragma unroll
                for (int nt = 0; nt < 4; nt++) {
#pragma unroll
                    for (int mt = 0; mt < 2; mt++) {
                        mma16(acc1[mt][nt], a[mt], b1[2 * nt], b1[2 * nt + 1]);
                        mma16(acc2[mt][nt], a[mt], b2[2 * nt], b2[2 * nt + 1]);
                    }
                }
            }
        }
        if (i + 1 < 16) {
#pragma unroll
            for (int j = 0; j < 8; j++) {
                int c = tid + j * 256;
                int k = c >> 5, n4 = c & 31;
                uint2 u;
                u.x = h2u(__floats2half2_rn(rbv[j].x, rbv[j].y));
                u.y = h2u(__floats2half2_rn(rbv[j].z, rbv[j].w));
                *(uint2*)(smem + B_OFF + nxt * B_STG + k * 272 + n4 * 8) = u;
            }
        }
        CP_WAIT0();
        __syncthreads();
    }

    // epilogue: swiglu fuse, store fp16 hidden
#pragma unroll
    for (int mt = 0; mt < 2; mt++) {
        int r0 = wm + mt * 16 + g;
        int s0 = slot[r0], s1 = slot[r0 + 8];
#pragma unroll
        for (int nt = 0; nt < 4; nt++) {
            int col = n0 + wn + nt * 8 + tg * 2;
            if (s0 >= 0) {
                float h1a = acc1[mt][nt][0], h2a = acc2[mt][nt][0];
                float h1b = acc1[mt][nt][1], h2b = acc2[mt][nt][1];
                float oa = h2a * h1a / (1.0f + expf(-h1a));
                float ob = h2b * h1b / (1.0f + expf(-h1b));
                *(uint32_t*)(g_hiddenh + (size_t)s0 * Hh + col) = h2u(__floats2half2_rn(oa, ob));
            }
            if (s1 >= 0) {
                float h1a = acc1[mt][nt][2], h2a = acc2[mt][nt][2];
                float h1b = acc1[mt][nt][3], h2b = acc2[mt][nt][3];
                float oa = h2a * h1a / (1.0f + expf(-h1a));
                float ob = h2b * h1b / (1.0f + expf(-h1b));
                *(uint32_t*)(g_hiddenh + (size_t)s1 * Hh + col) = h2u(__floats2half2_rn(oa, ob));
            }
        }
    }
}

// ======================= GEMM2 =======================
// out[tok, n] += wt[slot] * (hiddenh @ w3)[n] via atomics. CTA 128m x 128n. KC=64, 32 chunks.
__global__ void __launch_bounds__(256, 2) gemm2_kernel(const float* __restrict__ w3,
                                                       float* __restrict__ out, int out_size) {
    // aux-loss write (exactly once, before any early return)
    if (blockIdx.x == 0 && blockIdx.y == 0 && blockIdx.z == 0 && threadIdx.x == 0
        && out_size > T * D)
        out[T * D] = 0.01f * g_aux / (float)(T * E);

    int e = blockIdx.z;
    int cnt = g_cnt[e];
    int m0 = blockIdx.x * 128;
    if (m0 >= cnt) return;
    int n0 = blockIdx.y * 128;

    extern __shared__ char smem[];
    uint32_t sb = smem_u32(smem);
    int* slot = (int*)smem;
    int* srcs = (int*)(smem + 512);
    int tid = threadIdx.x, wid = tid >> 5, lane = tid & 31;
    int g = lane >> 2, tg = lane & 3;
    int wm = (wid & 3) * 32, wn = (wid >> 2) * 64;
    int q = lane >> 3, r = lane & 7;

    if (tid < 128) {
        int m = m0 + tid;
        int s = g_list[e][(m < cnt) ? m : 0];
        slot[tid] = (m < cnt) ? s : -1;
        srcs[tid] = s;
    }
    __syncthreads();

    const float* wb0 = w3 + (size_t)e * Hh * D + n0;
    uint32_t aBase = sb + A_OFF + (uint32_t)((wm + (q & 1) * 8 + r) * 144 + (q >> 1) * 16);
    uint32_t bBase = sb + B_OFF + (uint32_t)(((q & 1) * 8 + r) * 272 + (q >> 1) * 16);

    float4 rbv[8];

#pragma unroll
    for (int j = 0; j < 4; j++) {
        int c = tid + j * 256;
        int m = c >> 3, kq = c & 7;
        const __half* src = g_hiddenh + (size_t)srcs[m] * Hh + kq * 8;
        CP_ASYNC16(sb + A_OFF + m * 144 + kq * 16, src);
    }
    CP_COMMIT();
#pragma unroll
    for (int j = 0; j < 8; j++) {
        int c = tid + j * 256;
        int k = c >> 5, n4 = c & 31;
        rbv[j] = *(const float4*)(wb0 + (size_t)k * D + n4 * 4);
    }
#pragma unroll
    for (int j = 0; j < 8; j++) {
        int c = tid + j * 256;
        int k = c >> 5, n4 = c & 31;
        uint2 u;
        u.x = h2u(__floats2half2_rn(rbv[j].x, rbv[j].y));
        u.y = h2u(__floats2half2_rn(rbv[j].z, rbv[j].w));
        *(uint2*)(smem + B_OFF + k * 272 + n4 * 8) = u;
    }
    CP_WAIT0();
    __syncthreads();

    float acc[2][8][4] = {};

    for (int i = 0; i < 32; i++) {
        int cur = i & 1, nxt = cur ^ 1;
        if (i + 1 < 32) {
            int k0 = (i + 1) * 64;
#pragma unroll
            for (int j = 0; j < 4; j++) {
                int c = tid + j * 256;
                int m = c >> 3, kq = c & 7;
                const __half* src = g_hiddenh + (size_t)srcs[m] * Hh + k0 + kq * 8;
                CP_ASYNC16(sb + A_OFF + nxt * A_STG + m * 144 + kq * 16, src);
            }
            CP_COMMIT();
#pragma unroll
            for (int j = 0; j < 8; j++) {
                int c = tid + j * 256;
                int k = c >> 5, n4 = c & 31;
                rbv[j] = *(const float4*)(wb0 + (size_t)(k0 + k) * D + n4 * 4);
            }
        }
        {
            uint32_t aA = aBase + cur * A_STG;
            uint32_t bA = bBase + cur * B_STG;
#pragma unroll
            for (int kt = 0; kt < 4; kt++) {
                uint32_t a[2][4];
                ldsm4(a[0], aA + kt * 32);
                ldsm4(a[1], aA + kt * 32 + 16 * 144);
                uint32_t b[16];
                uint32_t bk = bA + kt * (16 * 272);
                ldsm4t(b + 0,  bk + (wn + 0) * 2);
                ldsm4t(b + 4,  bk + (wn + 16) * 2);
                ldsm4t(b + 8,  bk + (wn + 32) * 2);
                ldsm4t(b + 12, bk + (wn + 48) * 2);
#pragma unroll
                for (int nt = 0; nt < 8; nt++) {
#pragma unroll
                    for (int mt = 0; mt < 2; mt++)
                        mma16(acc[mt][nt], a[mt], b[2 * nt], b[2 * nt + 1]);
                }
            }
        }
        if (i + 1 < 32) {
#pragma unroll
            for (int j = 0; j < 8; j++) {
                int c = tid + j * 256;
                int k = c >> 5, n4 = c & 31;
                uint2 u;
                u.x = h2u(__floats2half2_rn(rbv[j].x, rbv[j].y));
                u.y = h2u(__floats2half2_rn(rbv[j].z, rbv[j].w));
                *(uint2*)(smem + B_OFF + nxt * B_STG + k * 272 + n4 * 8) = u;
            }
        }
        CP_WAIT0();
        __syncthreads();
    }

    // epilogue: weighted atomic accumulate into out (2 contributions/element total)
#pragma unroll
    for (int mt = 0; mt < 2; mt++) {
        int r0 = wm + mt * 16 + g;
        int s0 = slot[r0], s1 = slot[r0 + 8];
        float w0 = (s0 >= 0) ? g_wt[s0] : 0.0f;
        float w1 = (s1 >= 0) ? g_wt[s1] : 0.0f;
        float* o0 = (s0 >= 0) ? (out + (size_t)(s0 >> 1) * D) : 0;
        float* o1 = (s1 >= 0) ? (out + (size_t)(s1 >> 1) * D) : 0;
#pragma unroll
        for (int nt = 0; nt < 8; nt++) {
            int col = n0 + wn + nt * 8 + tg * 2;
            if (s0 >= 0) {
                atomicAdd(o0 + col,     w0 * acc[mt][nt][0]);
                atomicAdd(o0 + col + 1, w0 * acc[mt][nt][1]);
            }
            if (s1 >= 0) {
                atomicAdd(o1 + col,     w1 * acc[mt][nt][2]);
                atomicAdd(o1 + col + 1, w1 * acc[mt][nt][3]);
            }
        }
    }
}

// ======================= launch =======================
extern "C" void kernel_launch(void* const* d_in, const int* in_sizes, int n_in,
                              void* d_out, int out_size) {
    const float* x   = (const float*)d_in[0];
    const float* rw  = (const float*)d_in[1];
    const float* rb  = (const float*)d_in[2];
    const float* w12 = (const float*)d_in[3];
    const float* w3  = (const float*)d_in[4];
    float* out = (float*)d_out;

    cudaFuncSetAttribute(gemm1_kernel, cudaFuncAttributeMaxDynamicSharedMemorySize, G_SMEM);
    cudaFuncSetAttribute(gemm2_kernel, cudaFuncAttributeMaxDynamicSharedMemorySize, G_SMEM);

    zero_kernel<<<1, 32>>>();                                 // 0
    zero_out<<<(T * D / 4 + 255) / 256, 256>>>(out);          // 1
    router_kernel<<<T / 8, 256>>>(x, rw, rb);                 // 2 (also x->fp16)
    gemm1_kernel<<<dim3(16, 32, E), 256, G_SMEM>>>(w12);      // 3 (ncu slot)
    gemm2_kernel<<<dim3(16, 8, E), 256, G_SMEM>>>(w3, out, out_size); // 4
}